// round 15
// baseline (speedup 1.0000x reference)
#include <cuda_runtime.h>
#include <cuda_fp16.h>
#include <stdint.h>

#define BB 4
#define LL 4096
#define DD 256
#define AA 64
#define INFF 1e30f
#define LOG2E 1.4426950408889634f

typedef unsigned long long ull;

// ------------------------- fp16 split scratch ------------------------------
__device__ __align__(256) __half g_qhi[BB * LL * AA];
__device__ __align__(256) __half g_qlo[BB * LL * AA];
__device__ __align__(256) __half g_khi[BB * LL * AA];  // pre-scaled by log2e
__device__ __align__(256) __half g_klo[BB * LL * AA];
__device__ __align__(256) __half g_vhi[BB * LL * AA];  // single fp16
// W fp16 hi/lo (produced once by convert_kernel)
__device__ __align__(256) __half g_whi[DD * 192];      // [d][q|k|v]
__device__ __align__(256) __half g_wlo[DD * 192];

// ------------------------- PTX helpers -------------------------------------
__device__ __forceinline__ uint32_t smem_u32(const void* p) {
    uint32_t a;
    asm("{ .reg .u64 t; cvta.to.shared.u64 t, %1; cvt.u32.u64 %0, t; }"
        : "=r"(a) : "l"(p));
    return a;
}

#define SWZI(r, c4) (((r) << 7) + ((((c4) ^ ((r) & 7))) << 4))

__device__ __forceinline__ void ldsm4(unsigned r[4], uint32_t a) {
    asm volatile("ldmatrix.sync.aligned.m8n8.x4.shared.b16 {%0,%1,%2,%3}, [%4];"
        : "=r"(r[0]), "=r"(r[1]), "=r"(r[2]), "=r"(r[3]) : "r"(a));
}
__device__ __forceinline__ void ldsm4t(unsigned r[4], uint32_t a) {
    asm volatile("ldmatrix.sync.aligned.m8n8.x4.trans.shared.b16 {%0,%1,%2,%3}, [%4];"
        : "=r"(r[0]), "=r"(r[1]), "=r"(r[2]), "=r"(r[3]) : "r"(a));
}
__device__ __forceinline__ void mma16816(float d[4], const unsigned a[4],
                                         const unsigned b[2]) {
    asm volatile("mma.sync.aligned.m16n8k16.row.col.f32.f16.f16.f32 "
        "{%0,%1,%2,%3}, {%4,%5,%6,%7}, {%8,%9}, {%0,%1,%2,%3};"
        : "+f"(d[0]), "+f"(d[1]), "+f"(d[2]), "+f"(d[3])
        : "r"(a[0]), "r"(a[1]), "r"(a[2]), "r"(a[3]), "r"(b[0]), "r"(b[1]));
}
#define CP16(d, s) asm volatile("cp.async.cg.shared.global [%0], [%1], 16;" :: "r"(d), "l"(s))
#define CP_COMMIT() asm volatile("cp.async.commit_group;" ::: "memory")
#define CP_WAIT0()  asm volatile("cp.async.wait_group 0;" ::: "memory")

__device__ __forceinline__ float ex2f(float x) {
    float r;
    asm("ex2.approx.ftz.f32 %0, %1;" : "=f"(r) : "f"(x));
    return r;
}
// pack hi fp16x2, return lo residual fp16x2 via out-param
__device__ __forceinline__ unsigned pkhl(float a, float b, unsigned& lo) {
    __half2 h2 = __floats2half2_rn(a, b);
    float2 hf = __half22float2(h2);
    __half2 l2 = __floats2half2_rn(a - hf.x, b - hf.y);
    lo = *(unsigned*)&l2;
    return *(unsigned*)&h2;
}
// pack two floats to fp16x2 (no residual)
__device__ __forceinline__ unsigned pk16(float a, float b) {
    __half2 h2 = __floats2half2_rn(a, b);
    return *(unsigned*)&h2;
}

// ---------------------------------------------------------------------------
// Kernel 0: convert W to fp16 hi/lo (once). Wk folded with log2e.
// ---------------------------------------------------------------------------
__global__ __launch_bounds__(256) void convert_kernel(
    const float* __restrict__ Wq,
    const float* __restrict__ Wk,
    const float* __restrict__ Wv)
{
    int widx = blockIdx.x * 256 + threadIdx.x;     // 0..12287
    int mat = widx >> 12;
    int off = (widx & 4095) * 4;                   // float offset in [256][64]
    int d = off >> 6;
    int a = off & 63;
    const float* W = (mat == 0) ? Wq : (mat == 1) ? Wk : Wv;
    float s = (mat == 1) ? LOG2E : 1.f;
    float4 v = *(const float4*)&W[off];
    unsigned lo0, lo1;
    unsigned h0 = pkhl(v.x * s, v.y * s, lo0);
    unsigned h1 = pkhl(v.z * s, v.w * s, lo1);
    int o = d * 192 + mat * 64 + a;
    *(uint2*)&g_whi[o] = make_uint2(h0, h1);
    *(uint2*)&g_wlo[o] = make_uint2(lo0, lo1);
}

// ---------------------------------------------------------------------------
// Kernel 1: QKV projection GEMM on tensor cores (3-pass fp16 split).
// x loaded raw fp32 + converted in-kernel (consumed by exactly one CTA).
// ---------------------------------------------------------------------------
#define PSM_XH 0        // 64 x 64 fp16 (8KB)
#define PSM_XL 8192
#define PSM_WH 16384    // 3 mats x (64d x 64a) = 24KB
#define PSM_WL 40960
#define PSM_TOTAL 65536

extern __shared__ char smc[];

__global__ __launch_bounds__(128, 2) void qkv_gemm_kernel(
    const float* __restrict__ x)
{
    const uint32_t sb = smem_u32(smc);
    const int t    = threadIdx.x;
    const int w    = t >> 5;
    const int lane = t & 31;
    const int m0   = blockIdx.x * 64;

    float acc[3][8][4];
#pragma unroll
    for (int m = 0; m < 3; m++)
#pragma unroll
        for (int nt = 0; nt < 8; nt++)
#pragma unroll
            for (int e = 0; e < 4; e++) acc[m][nt][e] = 0.f;

    for (int d0 = 0; d0 < DD; d0 += 64) {
        __syncthreads();   // previous chunk's ldsm reads done
        // W chunk first (cp.async overlaps x LDG/convert below).
#pragma unroll
        for (int i = 0; i < 12; i++) {
            int idx = t + i * 128;
            int mat = idx >> 9;
            int rr  = idx & 511;
            int r   = rr >> 3;
            int c4  = rr & 7;
            size_t g = (size_t)(d0 + r) * 192 + mat * 64 + c4 * 8;
            uint32_t so = (uint32_t)(mat * 8192 + SWZI(r, c4));
            CP16(sb + PSM_WH + so, g_whi + g);
            CP16(sb + PSM_WL + so, g_wlo + g);
        }
        CP_COMMIT();
        // x tile: raw fp32 LDG, convert, swizzled STS.
#pragma unroll
        for (int i = 0; i < 4; i++) {
            int idx = t + i * 128;
            int r  = idx >> 3;
            int c4 = idx & 7;
            const float* src = &x[(size_t)(m0 + r) * DD + d0 + c4 * 8];
            float4 f0 = *(const float4*)&src[0];
            float4 f1 = *(const float4*)&src[4];
            uint4 hi, lo;
            hi.x = pkhl(f0.x, f0.y, lo.x);
            hi.y = pkhl(f0.z, f0.w, lo.y);
            hi.z = pkhl(f1.x, f1.y, lo.z);
            hi.w = pkhl(f1.z, f1.w, lo.w);
            int so = SWZI(r, c4);
            *(uint4*)(smc + PSM_XH + so) = hi;
            *(uint4*)(smc + PSM_XL + so) = lo;
        }
        CP_WAIT0();
        __syncthreads();

#pragma unroll
        for (int kt = 0; kt < 4; kt++) {
            unsigned ah[4], al[4];
            uint32_t qa = sb + PSM_XH +
                SWZI(w * 16 + (lane & 15), kt * 2 + (lane >> 4));
            ldsm4(ah, qa);
            ldsm4(al, qa + 8192);
#pragma unroll
            for (int mat = 0; mat < 3; mat++) {
#pragma unroll
                for (int c4t = 0; c4t < 4; c4t++) {
                    int r  = kt * 16 + (((lane >> 3) & 1) << 3) + (lane & 7);
                    int c4 = c4t * 2 + (lane >> 4);
                    unsigned bh[4], bl[4];
                    ldsm4t(bh, sb + PSM_WH + mat * 8192 + SWZI(r, c4));
                    ldsm4t(bl, sb + PSM_WL + mat * 8192 + SWZI(r, c4));
#pragma unroll
                    for (int ntl = 0; ntl < 2; ntl++)
                        mma16816(acc[mat][c4t * 2 + ntl], ah, bh + 2 * ntl);
#pragma unroll
                    for (int ntl = 0; ntl < 2; ntl++)
                        mma16816(acc[mat][c4t * 2 + ntl], al, bh + 2 * ntl);
#pragma unroll
                    for (int ntl = 0; ntl < 2; ntl++)
                        mma16816(acc[mat][c4t * 2 + ntl], ah, bl + 2 * ntl);
                }
            }
        }
    }

    // Epilogue: split to fp16 hi/lo (q,k) / single fp16 (v).
    const int g  = lane >> 2;
    const int tq = lane & 3;
    const size_t r0 = (size_t)(m0 + w * 16 + g);
    const size_t r1 = r0 + 8;
#pragma unroll
    for (int nt = 0; nt < 8; nt++) {
        int c = nt * 8 + 2 * tq;
        {
            unsigned lo0, lo1;
            unsigned h0 = pkhl(acc[0][nt][0], acc[0][nt][1], lo0);
            unsigned h1 = pkhl(acc[0][nt][2], acc[0][nt][3], lo1);
            *(unsigned*)&g_qhi[r0 * AA + c] = h0;
            *(unsigned*)&g_qlo[r0 * AA + c] = lo0;
            *(unsigned*)&g_qhi[r1 * AA + c] = h1;
            *(unsigned*)&g_qlo[r1 * AA + c] = lo1;
        }
        {
            unsigned lo0, lo1;
            unsigned h0 = pkhl(acc[1][nt][0], acc[1][nt][1], lo0);
            unsigned h1 = pkhl(acc[1][nt][2], acc[1][nt][3], lo1);
            *(unsigned*)&g_khi[r0 * AA + c] = h0;
            *(unsigned*)&g_klo[r0 * AA + c] = lo0;
            *(unsigned*)&g_khi[r1 * AA + c] = h1;
            *(unsigned*)&g_klo[r1 * AA + c] = lo1;
        }
        {
            __half2 v0 = __floats2half2_rn(acc[2][nt][0], acc[2][nt][1]);
            __half2 v1 = __floats2half2_rn(acc[2][nt][2], acc[2][nt][3]);
            *(__half2*)&g_vhi[r0 * AA + c] = v0;
            *(__half2*)&g_vhi[r1 * AA + c] = v1;
        }
    }
}

// ---------------------------------------------------------------------------
// Kernel 2: causal flash attention, fp16 mma.sync.
// TRIPLE-buffered K/V -> ONE barrier per step (prefetch (jt+1)%3 overwrites a
// buffer last read in step jt-2; the top barrier proves body jt-1 complete
// for all warps, hence jt-2 reads done). S: 3-pass split. PV: single pass.
// ---------------------------------------------------------------------------
#define SM_QH  0
#define SM_QL  8192
#define SM_KV  16384       // 3 bufs x 24KB: [KH 8K | KL 8K | VH 8K]
#define KVB    24576
#define SM_TOTAL (16384 + 3 * KVB)   // 90112

__device__ __forceinline__ void prefetch_kv(uint32_t sb, int buf, size_t gkb, int t)
{
    const uint32_t bb = sb + SM_KV + (uint32_t)buf * KVB;
#pragma unroll
    for (int i = 0; i < 4; i++) {
        int idx = t + i * 128;          // 0..511
        int r  = idx >> 3;
        int c4 = idx & 7;
        size_t g = gkb + (size_t)r * AA + c4 * 8;
        uint32_t so = (uint32_t)SWZI(r, c4);
        CP16(bb + so,         g_khi + g);
        CP16(bb + 8192 + so,  g_klo + g);
        CP16(bb + 16384 + so, g_vhi + g);
    }
}

__global__ __launch_bounds__(128, 2) void attn_kernel(float* __restrict__ out)
{
    const uint32_t sb = smem_u32(smc);
    const int t    = threadIdx.x;
    const int w    = t >> 5;
    const int lane = t & 31;

    // bid -> (tile, b): SM-pair (bid, bid+148) loads sum to 65 or 55 steps;
    // single-CTA SMs (bids 108..147) get mid tiles.
    const int bid = blockIdx.x;
    int tile, b;
    if (bid < 56)       { tile = bid >> 2;              b = bid & 3; }
    else if (bid < 108) { tile = 14 + ((bid - 56) >> 2); b = (bid - 56) & 3; }
    else if (bid < 148) { tile = 40 + ((bid - 108) >> 2); b = (bid - 108) & 3; }
    else if (bid < 204) { tile = 63 - ((bid - 148) >> 2); b = (bid - 148) & 3; }
    else                { tile = 39 - ((bid - 204) >> 2); b = (bid - 204) & 3; }

    const size_t gbase = (size_t)b * LL * AA;
    const int rb = tile * 64 + w * 16;

    prefetch_kv(sb, 0, gbase, t);
    CP_COMMIT();

    // Load Q tile (64 rows x 64 fp16, hi+lo).
#pragma unroll
    for (int i = 0; i < 4; i++) {
        int idx = t + i * 128;
        int r  = idx >> 3;
        int c4 = idx & 7;
        size_t g = gbase + (size_t)(tile * 64 + r) * AA + c4 * 8;
        int so = SWZI(r, c4);
        *(uint4*)(smc + SM_QH + so) = *(const uint4*)&g_qhi[g];
        *(uint4*)(smc + SM_QL + so) = *(const uint4*)&g_qlo[g];
    }

    float O[8][4];
    float mr[2], lr[2];
    mr[0] = mr[1] = -INFF;
    lr[0] = lr[1] = 0.f;
#pragma unroll
    for (int nt = 0; nt < 8; nt++)
#pragma unroll
        for (int e = 0; e < 4; e++) O[nt][e] = 0.f;

    const int g  = lane >> 2;
    const int tq = lane & 3;

    int buf = 0, nbuf = 1;
    for (int jt = 0; jt <= tile; jt++) {
        CP_WAIT0();
        __syncthreads();   // data for jt visible; body jt-1 done by all warps
        if (jt < tile) {
            prefetch_kv(sb, nbuf, gbase + (size_t)(jt + 1) * 64 * AA, t);
            CP_COMMIT();
        }
        const int kb = jt * 64;
        const bool diag = (jt == tile);

        float S[8][4];
#pragma unroll
        for (int nt = 0; nt < 8; nt++)
#pragma unroll
            for (int e = 0; e < 4; e++) S[nt][e] = 0.f;

        const uint32_t khb = sb + SM_KV + (uint32_t)buf * KVB;
        const uint32_t klb = khb + 8192;

        // ---- S = Q K^T: batch-load np fragments, pass-outermost MMAs ----
#pragma unroll
        for (int kt = 0; kt < 4; kt++) {
            unsigned qh4[4], ql4[4];
            uint32_t qa = sb + SM_QH +
                SWZI(w * 16 + (lane & 15), kt * 2 + (lane >> 4));
            ldsm4(qh4, qa);
            ldsm4(ql4, qa + 8192);
            unsigned kh4[4][4], kl4[4][4];
#pragma unroll
            for (int np = 0; np < 4; np++) {
                int r  = np * 16 + ((lane >> 4) << 3) + (lane & 7);
                int c4 = kt * 2 + ((lane >> 3) & 1);
                ldsm4(kh4[np], khb + SWZI(r, c4));
                ldsm4(kl4[np], klb + SWZI(r, c4));
            }
#pragma unroll
            for (int np = 0; np < 4; np++)
#pragma unroll
                for (int ntl = 0; ntl < 2; ntl++)
                    mma16816(S[2 * np + ntl], qh4, kh4[np] + 2 * ntl);
#pragma unroll
            for (int np = 0; np < 4; np++)
#pragma unroll
                for (int ntl = 0; ntl < 2; ntl++)
                    mma16816(S[2 * np + ntl], ql4, kh4[np] + 2 * ntl);
#pragma unroll
            for (int np = 0; np < 4; np++)
#pragma unroll
                for (int ntl = 0; ntl < 2; ntl++)
                    mma16816(S[2 * np + ntl], qh4, kl4[np] + 2 * ntl);
        }

        // ---- mask + row max + conditional O rescale ----
        int r0 = rb + g, r1 = r0 + 8;
        if (diag) {
#pragma unroll
            for (int nt = 0; nt < 8; nt++) {
                int col = kb + nt * 8 + 2 * tq;
                if (col     > r0) S[nt][0] = -INFF;
                if (col + 1 > r0) S[nt][1] = -INFF;
                if (col     > r1) S[nt][2] = -INFF;
                if (col + 1 > r1) S[nt][3] = -INFF;
            }
        }
        float m0 = -INFF, m1 = -INFF;
#pragma unroll
        for (int nt = 0; nt < 8; nt++) {
            m0 = fmaxf(m0, fmaxf(S[nt][0], S[nt][1]));
            m1 = fmaxf(m1, fmaxf(S[nt][2], S[nt][3]));
        }
        m0 = fmaxf(m0, __shfl_xor_sync(0xffffffffu, m0, 1));
        m0 = fmaxf(m0, __shfl_xor_sync(0xffffffffu, m0, 2));
        m1 = fmaxf(m1, __shfl_xor_sync(0xffffffffu, m1, 1));
        m1 = fmaxf(m1, __shfl_xor_sync(0xffffffffu, m1, 2));
        float mn0 = fmaxf(mr[0], m0), mn1 = fmaxf(mr[1], m1);
        float sc0 = ex2f(mr[0] - mn0), sc1 = ex2f(mr[1] - mn1);
        mr[0] = mn0; mr[1] = mn1;
        // exp2(0)==1 exactly -> skip rescale warp-uniformly when no row moved.
        if (__any_sync(0xffffffffu, (sc0 != 1.f) | (sc1 != 1.f))) {
#pragma unroll
            for (int nt = 0; nt < 8; nt++) {
                O[nt][0] *= sc0; O[nt][1] *= sc0;
                O[nt][2] *= sc1; O[nt][3] *= sc1;
            }
        }

        // ---- exp/pack + PV: single pass (P fp16) ----
        const uint32_t vhb = khb + 16384;
        float rs0 = 0.f, rs1 = 0.f;
#pragma unroll
        for (int kt = 0; kt < 4; kt++) {
            unsigned ph[4];
            {
                float e00 = ex2f(S[2*kt  ][0] - mn0);
                float e01 = ex2f(S[2*kt  ][1] - mn0);
                float e02 = ex2f(S[2*kt  ][2] - mn1);
                float e03 = ex2f(S[2*kt  ][3] - mn1);
                float e10 = ex2f(S[2*kt+1][0] - mn0);
                float e11 = ex2f(S[2*kt+1][1] - mn0);
                float e12 = ex2f(S[2*kt+1][2] - mn1);
                float e13 = ex2f(S[2*kt+1][3] - mn1);
                rs0 += (e00 + e01) + (e10 + e11);
                rs1 += (e02 + e03) + (e12 + e13);
                ph[0] = pk16(e00, e01);
                ph[1] = pk16(e02, e03);
                ph[2] = pk16(e10, e11);
                ph[3] = pk16(e12, e13);
            }
            unsigned vh4[4][4];
#pragma unroll
            for (int np = 0; np < 4; np++) {
                int r  = kt * 16 + (((lane >> 3) & 1) << 3) + (lane & 7);
                int c4 = np * 2 + (lane >> 4);
                ldsm4t(vh4[np], vhb + SWZI(r, c4));
            }
#pragma unroll
            for (int np = 0; np < 4; np++)
#pragma unroll
                for (int ntl = 0; ntl < 2; ntl++)
                    mma16816(O[2 * np + ntl], ph, vh4[np] + 2 * ntl);
        }

        rs0 += __shfl_xor_sync(0xffffffffu, rs0, 1);
        rs0 += __shfl_xor_sync(0xffffffffu, rs0, 2);
        rs1 += __shfl_xor_sync(0xffffffffu, rs1, 1);
        rs1 += __shfl_xor_sync(0xffffffffu, rs1, 2);
        lr[0] = lr[0] * sc0 + rs0;
        lr[1] = lr[1] * sc1 + rs1;

        // rotate buffers (no bottom barrier: 3-deep ring + top barrier)
        buf = nbuf;
        nbuf = (nbuf == 2) ? 0 : nbuf + 1;
    }

    // ---- epilogue ----
    float i0 = 1.f / lr[0], i1 = 1.f / lr[1];
    size_t r0 = (size_t)(rb + g), r1 = r0 + 8;
#pragma unroll
    for (int nt = 0; nt < 8; nt++) {
        *(float2*)&out[gbase + r0 * AA + nt * 8 + 2 * tq] =
            make_float2(O[nt][0] * i0, O[nt][1] * i0);
        *(float2*)&out[gbase + r1 * AA + nt * 8 + 2 * tq] =
            make_float2(O[nt][2] * i1, O[nt][3] * i1);
    }
}

// ---------------------------------------------------------------------------
extern "C" void kernel_launch(void* const* d_in, const int* in_sizes, int n_in,
                              void* d_out, int out_size)
{
    const float* x  = (const float*)d_in[0];
    const float* Wq = (const float*)d_in[1];
    const float* Wk = (const float*)d_in[2];
    const float* Wv = (const float*)d_in[3];
    float* out = (float*)d_out;

    convert_kernel<<<48, 256>>>(Wq, Wk, Wv);

    cudaFuncSetAttribute(qkv_gemm_kernel,
                         cudaFuncAttributeMaxDynamicSharedMemorySize, PSM_TOTAL);
    qkv_gemm_kernel<<<256, 128, PSM_TOTAL>>>(x);

    cudaFuncSetAttribute(attn_kernel,
                         cudaFuncAttributeMaxDynamicSharedMemorySize, SM_TOTAL);
    attn_kernel<<<256, 128, SM_TOTAL>>>(out);
}

// round 16
// speedup vs baseline: 1.0608x; 1.0608x over previous
#include <cuda_runtime.h>
#include <cuda_fp16.h>
#include <stdint.h>

#define BB 4
#define LL 4096
#define DD 256
#define AA 64
#define INFF 1e30f
#define LOG2E 1.4426950408889634f

typedef unsigned long long ull;

// ------------------------- fp16 split scratch ------------------------------
__device__ __align__(256) __half g_qhi[BB * LL * AA];
__device__ __align__(256) __half g_qlo[BB * LL * AA];
__device__ __align__(256) __half g_khi[BB * LL * AA];  // pre-scaled by log2e
__device__ __align__(256) __half g_klo[BB * LL * AA];
__device__ __align__(256) __half g_vhi[BB * LL * AA];  // single fp16
// W fp16 hi/lo (produced once by convert_kernel)
__device__ __align__(256) __half g_whi[DD * 192];      // [d][q|k|v]
__device__ __align__(256) __half g_wlo[DD * 192];

// ------------------------- PTX helpers -------------------------------------
__device__ __forceinline__ uint32_t smem_u32(const void* p) {
    uint32_t a;
    asm("{ .reg .u64 t; cvta.to.shared.u64 t, %1; cvt.u32.u64 %0, t; }"
        : "=r"(a) : "l"(p));
    return a;
}

#define SWZI(r, c4) (((r) << 7) + ((((c4) ^ ((r) & 7))) << 4))

__device__ __forceinline__ void ldsm4(unsigned r[4], uint32_t a) {
    asm volatile("ldmatrix.sync.aligned.m8n8.x4.shared.b16 {%0,%1,%2,%3}, [%4];"
        : "=r"(r[0]), "=r"(r[1]), "=r"(r[2]), "=r"(r[3]) : "r"(a));
}
__device__ __forceinline__ void ldsm4t(unsigned r[4], uint32_t a) {
    asm volatile("ldmatrix.sync.aligned.m8n8.x4.trans.shared.b16 {%0,%1,%2,%3}, [%4];"
        : "=r"(r[0]), "=r"(r[1]), "=r"(r[2]), "=r"(r[3]) : "r"(a));
}
__device__ __forceinline__ void mma16816(float d[4], const unsigned a[4],
                                         const unsigned b[2]) {
    asm volatile("mma.sync.aligned.m16n8k16.row.col.f32.f16.f16.f32 "
        "{%0,%1,%2,%3}, {%4,%5,%6,%7}, {%8,%9}, {%0,%1,%2,%3};"
        : "+f"(d[0]), "+f"(d[1]), "+f"(d[2]), "+f"(d[3])
        : "r"(a[0]), "r"(a[1]), "r"(a[2]), "r"(a[3]), "r"(b[0]), "r"(b[1]));
}
#define CP16(d, s) asm volatile("cp.async.cg.shared.global [%0], [%1], 16;" :: "r"(d), "l"(s))
#define CP_COMMIT() asm volatile("cp.async.commit_group;" ::: "memory")
#define CP_WAIT0()  asm volatile("cp.async.wait_group 0;" ::: "memory")

__device__ __forceinline__ float ex2f(float x) {
    float r;
    asm("ex2.approx.ftz.f32 %0, %1;" : "=f"(r) : "f"(x));
    return r;
}
// pack hi fp16x2, return lo residual fp16x2 via out-param
__device__ __forceinline__ unsigned pkhl(float a, float b, unsigned& lo) {
    __half2 h2 = __floats2half2_rn(a, b);
    float2 hf = __half22float2(h2);
    __half2 l2 = __floats2half2_rn(a - hf.x, b - hf.y);
    lo = *(unsigned*)&l2;
    return *(unsigned*)&h2;
}
// pack two floats to fp16x2 (no residual)
__device__ __forceinline__ unsigned pk16(float a, float b) {
    __half2 h2 = __floats2half2_rn(a, b);
    return *(unsigned*)&h2;
}

// ---------------------------------------------------------------------------
// Kernel 0: convert W to fp16 hi/lo (once). Wk folded with log2e.
// ---------------------------------------------------------------------------
__global__ __launch_bounds__(256) void convert_kernel(
    const float* __restrict__ Wq,
    const float* __restrict__ Wk,
    const float* __restrict__ Wv)
{
    int widx = blockIdx.x * 256 + threadIdx.x;     // 0..12287
    int mat = widx >> 12;
    int off = (widx & 4095) * 4;                   // float offset in [256][64]
    int d = off >> 6;
    int a = off & 63;
    const float* W = (mat == 0) ? Wq : (mat == 1) ? Wk : Wv;
    float s = (mat == 1) ? LOG2E : 1.f;
    float4 v = *(const float4*)&W[off];
    unsigned lo0, lo1;
    unsigned h0 = pkhl(v.x * s, v.y * s, lo0);
    unsigned h1 = pkhl(v.z * s, v.w * s, lo1);
    int o = d * 192 + mat * 64 + a;
    *(uint2*)&g_whi[o] = make_uint2(h0, h1);
    *(uint2*)&g_wlo[o] = make_uint2(lo0, lo1);
}

// ---------------------------------------------------------------------------
// Kernel 1: QKV projection GEMM on tensor cores (3-pass fp16 split).
// ---------------------------------------------------------------------------
#define PSM_XH 0        // 64 x 64 fp16 (8KB)
#define PSM_XL 8192
#define PSM_WH 16384    // 3 mats x (64d x 64a) = 24KB
#define PSM_WL 40960
#define PSM_TOTAL 65536

extern __shared__ char smc[];

__global__ __launch_bounds__(128, 2) void qkv_gemm_kernel(
    const float* __restrict__ x)
{
    const uint32_t sb = smem_u32(smc);
    const int t    = threadIdx.x;
    const int w    = t >> 5;
    const int lane = t & 31;
    const int m0   = blockIdx.x * 64;

    float acc[3][8][4];
#pragma unroll
    for (int m = 0; m < 3; m++)
#pragma unroll
        for (int nt = 0; nt < 8; nt++)
#pragma unroll
            for (int e = 0; e < 4; e++) acc[m][nt][e] = 0.f;

    for (int d0 = 0; d0 < DD; d0 += 64) {
        __syncthreads();
#pragma unroll
        for (int i = 0; i < 12; i++) {
            int idx = t + i * 128;
            int mat = idx >> 9;
            int rr  = idx & 511;
            int r   = rr >> 3;
            int c4  = rr & 7;
            size_t g = (size_t)(d0 + r) * 192 + mat * 64 + c4 * 8;
            uint32_t so = (uint32_t)(mat * 8192 + SWZI(r, c4));
            CP16(sb + PSM_WH + so, g_whi + g);
            CP16(sb + PSM_WL + so, g_wlo + g);
        }
        CP_COMMIT();
#pragma unroll
        for (int i = 0; i < 4; i++) {
            int idx = t + i * 128;
            int r  = idx >> 3;
            int c4 = idx & 7;
            const float* src = &x[(size_t)(m0 + r) * DD + d0 + c4 * 8];
            float4 f0 = *(const float4*)&src[0];
            float4 f1 = *(const float4*)&src[4];
            uint4 hi, lo;
            hi.x = pkhl(f0.x, f0.y, lo.x);
            hi.y = pkhl(f0.z, f0.w, lo.y);
            hi.z = pkhl(f1.x, f1.y, lo.z);
            hi.w = pkhl(f1.z, f1.w, lo.w);
            int so = SWZI(r, c4);
            *(uint4*)(smc + PSM_XH + so) = hi;
            *(uint4*)(smc + PSM_XL + so) = lo;
        }
        CP_WAIT0();
        __syncthreads();

#pragma unroll
        for (int kt = 0; kt < 4; kt++) {
            unsigned ah[4], al[4];
            uint32_t qa = sb + PSM_XH +
                SWZI(w * 16 + (lane & 15), kt * 2 + (lane >> 4));
            ldsm4(ah, qa);
            ldsm4(al, qa + 8192);
#pragma unroll
            for (int mat = 0; mat < 3; mat++) {
#pragma unroll
                for (int c4t = 0; c4t < 4; c4t++) {
                    int r  = kt * 16 + (((lane >> 3) & 1) << 3) + (lane & 7);
                    int c4 = c4t * 2 + (lane >> 4);
                    unsigned bh[4], bl[4];
                    ldsm4t(bh, sb + PSM_WH + mat * 8192 + SWZI(r, c4));
                    ldsm4t(bl, sb + PSM_WL + mat * 8192 + SWZI(r, c4));
#pragma unroll
                    for (int ntl = 0; ntl < 2; ntl++)
                        mma16816(acc[mat][c4t * 2 + ntl], ah, bh + 2 * ntl);
#pragma unroll
                    for (int ntl = 0; ntl < 2; ntl++)
                        mma16816(acc[mat][c4t * 2 + ntl], al, bh + 2 * ntl);
#pragma unroll
                    for (int ntl = 0; ntl < 2; ntl++)
                        mma16816(acc[mat][c4t * 2 + ntl], ah, bl + 2 * ntl);
                }
            }
        }
    }

    const int g  = lane >> 2;
    const int tq = lane & 3;
    const size_t r0 = (size_t)(m0 + w * 16 + g);
    const size_t r1 = r0 + 8;
#pragma unroll
    for (int nt = 0; nt < 8; nt++) {
        int c = nt * 8 + 2 * tq;
        {
            unsigned lo0, lo1;
            unsigned h0 = pkhl(acc[0][nt][0], acc[0][nt][1], lo0);
            unsigned h1 = pkhl(acc[0][nt][2], acc[0][nt][3], lo1);
            *(unsigned*)&g_qhi[r0 * AA + c] = h0;
            *(unsigned*)&g_qlo[r0 * AA + c] = lo0;
            *(unsigned*)&g_qhi[r1 * AA + c] = h1;
            *(unsigned*)&g_qlo[r1 * AA + c] = lo1;
        }
        {
            unsigned lo0, lo1;
            unsigned h0 = pkhl(acc[1][nt][0], acc[1][nt][1], lo0);
            unsigned h1 = pkhl(acc[1][nt][2], acc[1][nt][3], lo1);
            *(unsigned*)&g_khi[r0 * AA + c] = h0;
            *(unsigned*)&g_klo[r0 * AA + c] = lo0;
            *(unsigned*)&g_khi[r1 * AA + c] = h1;
            *(unsigned*)&g_klo[r1 * AA + c] = lo1;
        }
        {
            __half2 v0 = __floats2half2_rn(acc[2][nt][0], acc[2][nt][1]);
            __half2 v1 = __floats2half2_rn(acc[2][nt][2], acc[2][nt][3]);
            *(__half2*)&g_vhi[r0 * AA + c] = v0;
            *(__half2*)&g_vhi[r1 * AA + c] = v1;
        }
    }
}

// ---------------------------------------------------------------------------
// Kernel 2: causal flash attention, fp16 mma.sync, 128-wide k-tiles.
// Q fragments hoisted out of the main loop (jt-invariant). Per step:
// S[16][4] over 128 k-cols (3-pass split), softmax, PV (single pass).
// nsteps = ceil((tile+1)/2); pair (c,63-c) sums to constant 34 steps.
// ---------------------------------------------------------------------------
#define SM_QH  0
#define SM_QL  8192
#define SM_KV  16384       // 2 bufs x 48KB: [KH 16K | KL 16K | VH 16K]
#define KVB    49152
#define SM_TOTAL (16384 + 2 * KVB)   // 114688 B = 112 KB

__device__ __forceinline__ void prefetch_kv(uint32_t sb, int buf, size_t gkb, int t)
{
    const uint32_t bb = sb + SM_KV + (uint32_t)buf * KVB;
#pragma unroll
    for (int i = 0; i < 8; i++) {
        int idx = t + i * 128;          // 0..1023 (128 rows x 8 c4)
        int r  = idx >> 3;
        int c4 = idx & 7;
        size_t g = gkb + (size_t)r * AA + c4 * 8;
        uint32_t so = (uint32_t)SWZI(r, c4);
        CP16(bb + so,         g_khi + g);
        CP16(bb + 16384 + so, g_klo + g);
        CP16(bb + 32768 + so, g_vhi + g);
    }
}

__global__ __launch_bounds__(128, 2) void attn_kernel(float* __restrict__ out)
{
    const uint32_t sb = smem_u32(smc);
    const int t    = threadIdx.x;
    const int w    = t >> 5;
    const int lane = t & 31;

    // bid -> (tile, b): pair-sums of ceil((tile+1)/2) are constant 34.
    const int bid = blockIdx.x;
    int tile, b;
    if (bid < 56)       { tile = bid >> 2;              b = bid & 3; }
    else if (bid < 108) { tile = 14 + ((bid - 56) >> 2); b = (bid - 56) & 3; }
    else if (bid < 148) { tile = 40 + ((bid - 108) >> 2); b = (bid - 108) & 3; }
    else if (bid < 204) { tile = 63 - ((bid - 148) >> 2); b = (bid - 148) & 3; }
    else                { tile = 39 - ((bid - 204) >> 2); b = (bid - 204) & 3; }

    const size_t gbase = (size_t)b * LL * AA;
    const int rb = tile * 64 + w * 16;
    const int nsteps = (tile + 2) >> 1;    // ceil((tile+1)/2)

    prefetch_kv(sb, 0, gbase, t);
    CP_COMMIT();

    // Load Q tile (64 rows x 64 fp16, hi+lo) into its own smem region.
#pragma unroll
    for (int i = 0; i < 4; i++) {
        int idx = t + i * 128;
        int r  = idx >> 3;
        int c4 = idx & 7;
        size_t g = gbase + (size_t)(tile * 64 + r) * AA + c4 * 8;
        int so = SWZI(r, c4);
        *(uint4*)(smc + SM_QH + so) = *(const uint4*)&g_qhi[g];
        *(uint4*)(smc + SM_QL + so) = *(const uint4*)&g_qlo[g];
    }
    __syncthreads();

    // Hoist Q fragments (jt-invariant).
    unsigned qh4[4][4], ql4[4][4];
#pragma unroll
    for (int kt = 0; kt < 4; kt++) {
        uint32_t qa = sb + SM_QH +
            SWZI(w * 16 + (lane & 15), kt * 2 + (lane >> 4));
        ldsm4(qh4[kt], qa);
        ldsm4(ql4[kt], qa + 8192);
    }

    float O[8][4];
    float mr[2], lr[2];
    mr[0] = mr[1] = -INFF;
    lr[0] = lr[1] = 0.f;
#pragma unroll
    for (int nt = 0; nt < 8; nt++)
#pragma unroll
        for (int e = 0; e < 4; e++) O[nt][e] = 0.f;

    const int g  = lane >> 2;
    const int tq = lane & 3;

    for (int jt = 0; jt < nsteps; jt++) {
        const int buf = jt & 1;
        CP_WAIT0();
        __syncthreads();
        if (jt + 1 < nsteps) {
            prefetch_kv(sb, buf ^ 1, gbase + (size_t)(jt + 1) * 128 * AA, t);
            CP_COMMIT();
        }
        const int kb = jt * 128;
        const bool diag = (jt == nsteps - 1);

        float S[16][4];
#pragma unroll
        for (int nt = 0; nt < 16; nt++)
#pragma unroll
            for (int e = 0; e < 4; e++) S[nt][e] = 0.f;

        const uint32_t khb = sb + SM_KV + (uint32_t)buf * KVB;
        const uint32_t klb = khb + 16384;

        // ---- S = Q K^T over 128 k-cols: np in two groups of 4 ----
#pragma unroll
        for (int kt = 0; kt < 4; kt++) {
#pragma unroll
            for (int grp = 0; grp < 2; grp++) {
                unsigned kh4[4][4], kl4[4][4];
#pragma unroll
                for (int n4 = 0; n4 < 4; n4++) {
                    int np = grp * 4 + n4;
                    int r  = np * 16 + ((lane >> 4) << 3) + (lane & 7);
                    int c4 = kt * 2 + ((lane >> 3) & 1);
                    ldsm4(kh4[n4], khb + SWZI(r, c4));
                    ldsm4(kl4[n4], klb + SWZI(r, c4));
                }
#pragma unroll
                for (int n4 = 0; n4 < 4; n4++)
#pragma unroll
                    for (int ntl = 0; ntl < 2; ntl++)
                        mma16816(S[grp * 8 + 2 * n4 + ntl], qh4[kt], kh4[n4] + 2 * ntl);
#pragma unroll
                for (int n4 = 0; n4 < 4; n4++)
#pragma unroll
                    for (int ntl = 0; ntl < 2; ntl++)
                        mma16816(S[grp * 8 + 2 * n4 + ntl], ql4[kt], kh4[n4] + 2 * ntl);
#pragma unroll
                for (int n4 = 0; n4 < 4; n4++)
#pragma unroll
                    for (int ntl = 0; ntl < 2; ntl++)
                        mma16816(S[grp * 8 + 2 * n4 + ntl], qh4[kt], kl4[n4] + 2 * ntl);
            }
        }

        // ---- mask + row max + conditional O rescale ----
        int r0 = rb + g, r1 = r0 + 8;
        if (diag) {
#pragma unroll
            for (int nt = 0; nt < 16; nt++) {
                int col = kb + nt * 8 + 2 * tq;
                if (col     > r0) S[nt][0] = -INFF;
                if (col + 1 > r0) S[nt][1] = -INFF;
                if (col     > r1) S[nt][2] = -INFF;
                if (col + 1 > r1) S[nt][3] = -INFF;
            }
        }
        float m0 = -INFF, m1 = -INFF;
#pragma unroll
        for (int nt = 0; nt < 16; nt++) {
            m0 = fmaxf(m0, fmaxf(S[nt][0], S[nt][1]));
            m1 = fmaxf(m1, fmaxf(S[nt][2], S[nt][3]));
        }
        m0 = fmaxf(m0, __shfl_xor_sync(0xffffffffu, m0, 1));
        m0 = fmaxf(m0, __shfl_xor_sync(0xffffffffu, m0, 2));
        m1 = fmaxf(m1, __shfl_xor_sync(0xffffffffu, m1, 1));
        m1 = fmaxf(m1, __shfl_xor_sync(0xffffffffu, m1, 2));
        float mn0 = fmaxf(mr[0], m0), mn1 = fmaxf(mr[1], m1);
        float sc0 = ex2f(mr[0] - mn0), sc1 = ex2f(mr[1] - mn1);
        mr[0] = mn0; mr[1] = mn1;
        if (__any_sync(0xffffffffu, (sc0 != 1.f) | (sc1 != 1.f))) {
#pragma unroll
            for (int nt = 0; nt < 8; nt++) {
                O[nt][0] *= sc0; O[nt][1] *= sc0;
                O[nt][2] *= sc1; O[nt][3] *= sc1;
            }
        }

        // ---- exp/pack + PV (single pass, contraction over 128 P cols) ----
        const uint32_t vhb = khb + 32768;
        float rs0 = 0.f, rs1 = 0.f;
#pragma unroll
        for (int ktp = 0; ktp < 8; ktp++) {
            unsigned ph[4];
            {
                float e00 = ex2f(S[2*ktp  ][0] - mn0);
                float e01 = ex2f(S[2*ktp  ][1] - mn0);
                float e02 = ex2f(S[2*ktp  ][2] - mn1);
                float e03 = ex2f(S[2*ktp  ][3] - mn1);
                float e10 = ex2f(S[2*ktp+1][0] - mn0);
                float e11 = ex2f(S[2*ktp+1][1] - mn0);
                float e12 = ex2f(S[2*ktp+1][2] - mn1);
                float e13 = ex2f(S[2*ktp+1][3] - mn1);
                rs0 += (e00 + e01) + (e10 + e11);
                rs1 += (e02 + e03) + (e12 + e13);
                ph[0] = pk16(e00, e01);
                ph[1] = pk16(e02, e03);
                ph[2] = pk16(e10, e11);
                ph[3] = pk16(e12, e13);
            }
            unsigned vh4[4][4];
#pragma unroll
            for (int np = 0; np < 4; np++) {
                int r  = ktp * 16 + (((lane >> 3) & 1) << 3) + (lane & 7);
                int c4 = np * 2 + (lane >> 4);
                ldsm4t(vh4[np], vhb + SWZI(r, c4));
            }
#pragma unroll
            for (int np = 0; np < 4; np++)
#pragma unroll
                for (int ntl = 0; ntl < 2; ntl++)
                    mma16816(O[2 * np + ntl], ph, vh4[np] + 2 * ntl);
        }

        rs0 += __shfl_xor_sync(0xffffffffu, rs0, 1);
        rs0 += __shfl_xor_sync(0xffffffffu, rs0, 2);
        rs1 += __shfl_xor_sync(0xffffffffu, rs1, 1);
        rs1 += __shfl_xor_sync(0xffffffffu, rs1, 2);
        lr[0] = lr[0] * sc0 + rs0;
        lr[1] = lr[1] * sc1 + rs1;

        __syncthreads();
    }

    // ---- epilogue ----
    float i0 = 1.f / lr[0], i1 = 1.f / lr[1];
    size_t r0 = (size_t)(rb + g), r1 = r0 + 8;
#pragma unroll
    for (int nt = 0; nt < 8; nt++) {
        *(float2*)&out[gbase + r0 * AA + nt * 8 + 2 * tq] =
            make_float2(O[nt][0] * i0, O[nt][1] * i0);
        *(float2*)&out[gbase + r1 * AA + nt * 8 + 2 * tq] =
            make_float2(O[nt][2] * i1, O[nt][3] * i1);
    }
}

// ---------------------------------------------------------------------------
extern "C" void kernel_launch(void* const* d_in, const int* in_sizes, int n_in,
                              void* d_out, int out_size)
{
    const float* x  = (const float*)d_in[0];
    const float* Wq = (const float*)d_in[1];
    const float* Wk = (const float*)d_in[2];
    const float* Wv = (const float*)d_in[3];
    float* out = (float*)d_out;

    convert_kernel<<<48, 256>>>(Wq, Wk, Wv);

    cudaFuncSetAttribute(qkv_gemm_kernel,
                         cudaFuncAttributeMaxDynamicSharedMemorySize, PSM_TOTAL);
    qkv_gemm_kernel<<<256, 128, PSM_TOTAL>>>(x);

    cudaFuncSetAttribute(attn_kernel,
                         cudaFuncAttributeMaxDynamicSharedMemorySize, SM_TOTAL);
    attn_kernel<<<256, 128, SM_TOTAL>>>(out);
}

// round 17
// speedup vs baseline: 1.1111x; 1.0474x over previous
#include <cuda_runtime.h>
#include <cuda_fp16.h>
#include <stdint.h>

#define BB 4
#define LL 4096
#define DD 256
#define AA 64
#define INFF 1e30f
#define LOG2E 1.4426950408889634f

typedef unsigned long long ull;

// ------------------------- fp16 split scratch ------------------------------
__device__ __align__(256) __half g_qhi[BB * LL * AA];
__device__ __align__(256) __half g_qlo[BB * LL * AA];
__device__ __align__(256) __half g_khi[BB * LL * AA];  // pre-scaled by log2e
__device__ __align__(256) __half g_klo[BB * LL * AA];
__device__ __align__(256) __half g_vhi[BB * LL * AA];  // single fp16
// W fp16 hi/lo (produced once by convert_kernel)
__device__ __align__(256) __half g_whi[DD * 192];      // [d][q|k|v]
__device__ __align__(256) __half g_wlo[DD * 192];

// ------------------------- PTX helpers -------------------------------------
__device__ __forceinline__ uint32_t smem_u32(const void* p) {
    uint32_t a;
    asm("{ .reg .u64 t; cvta.to.shared.u64 t, %1; cvt.u32.u64 %0, t; }"
        : "=r"(a) : "l"(p));
    return a;
}

#define SWZI(r, c4) (((r) << 7) + ((((c4) ^ ((r) & 7))) << 4))

__device__ __forceinline__ void ldsm4(unsigned r[4], uint32_t a) {
    asm volatile("ldmatrix.sync.aligned.m8n8.x4.shared.b16 {%0,%1,%2,%3}, [%4];"
        : "=r"(r[0]), "=r"(r[1]), "=r"(r[2]), "=r"(r[3]) : "r"(a));
}
__device__ __forceinline__ void ldsm4t(unsigned r[4], uint32_t a) {
    asm volatile("ldmatrix.sync.aligned.m8n8.x4.trans.shared.b16 {%0,%1,%2,%3}, [%4];"
        : "=r"(r[0]), "=r"(r[1]), "=r"(r[2]), "=r"(r[3]) : "r"(a));
}
__device__ __forceinline__ void mma16816(float d[4], const unsigned a[4],
                                         const unsigned b[2]) {
    asm volatile("mma.sync.aligned.m16n8k16.row.col.f32.f16.f16.f32 "
        "{%0,%1,%2,%3}, {%4,%5,%6,%7}, {%8,%9}, {%0,%1,%2,%3};"
        : "+f"(d[0]), "+f"(d[1]), "+f"(d[2]), "+f"(d[3])
        : "r"(a[0]), "r"(a[1]), "r"(a[2]), "r"(a[3]), "r"(b[0]), "r"(b[1]));
}
#define CP16(d, s) asm volatile("cp.async.cg.shared.global [%0], [%1], 16;" :: "r"(d), "l"(s))
#define CP_COMMIT() asm volatile("cp.async.commit_group;" ::: "memory")
#define CP_WAIT0()  asm volatile("cp.async.wait_group 0;" ::: "memory")

__device__ __forceinline__ float ex2f(float x) {
    float r;
    asm("ex2.approx.ftz.f32 %0, %1;" : "=f"(r) : "f"(x));
    return r;
}
// pack hi fp16x2, return lo residual fp16x2 via out-param
__device__ __forceinline__ unsigned pkhl(float a, float b, unsigned& lo) {
    __half2 h2 = __floats2half2_rn(a, b);
    float2 hf = __half22float2(h2);
    __half2 l2 = __floats2half2_rn(a - hf.x, b - hf.y);
    lo = *(unsigned*)&l2;
    return *(unsigned*)&h2;
}
// pack two floats to fp16x2 (no residual)
__device__ __forceinline__ unsigned pk16(float a, float b) {
    __half2 h2 = __floats2half2_rn(a, b);
    return *(unsigned*)&h2;
}

// ---------------------------------------------------------------------------
// Kernel 0: convert W to fp16 hi/lo (once). Wk folded with log2e.
// ---------------------------------------------------------------------------
__global__ __launch_bounds__(256) void convert_kernel(
    const float* __restrict__ Wq,
    const float* __restrict__ Wk,
    const float* __restrict__ Wv)
{
    int widx = blockIdx.x * 256 + threadIdx.x;     // 0..12287
    int mat = widx >> 12;
    int off = (widx & 4095) * 4;                   // float offset in [256][64]
    int d = off >> 6;
    int a = off & 63;
    const float* W = (mat == 0) ? Wq : (mat == 1) ? Wk : Wv;
    float s = (mat == 1) ? LOG2E : 1.f;
    float4 v = *(const float4*)&W[off];
    unsigned lo0, lo1;
    unsigned h0 = pkhl(v.x * s, v.y * s, lo0);
    unsigned h1 = pkhl(v.z * s, v.w * s, lo1);
    int o = d * 192 + mat * 64 + a;
    *(uint2*)&g_whi[o] = make_uint2(h0, h1);
    *(uint2*)&g_wlo[o] = make_uint2(lo0, lo1);
}

// ---------------------------------------------------------------------------
// Kernel 1: QKV projection GEMM on tensor cores.
// q,k: 3-pass fp16 split (precision-critical). v: SINGLE pass (stored as
// single fp16 anyway; 1-pass error ~2^-11 matches the accepted quantization).
// ---------------------------------------------------------------------------
#define PSM_XH 0        // 64 x 64 fp16 (8KB)
#define PSM_XL 8192
#define PSM_WH 16384    // 3 mats x (64d x 64a) = 24KB
#define PSM_WL 40960
#define PSM_TOTAL 65536

extern __shared__ char smc[];

__global__ __launch_bounds__(128, 2) void qkv_gemm_kernel(
    const float* __restrict__ x)
{
    const uint32_t sb = smem_u32(smc);
    const int t    = threadIdx.x;
    const int w    = t >> 5;
    const int lane = t & 31;
    const int m0   = blockIdx.x * 64;

    float acc[3][8][4];
#pragma unroll
    for (int m = 0; m < 3; m++)
#pragma unroll
        for (int nt = 0; nt < 8; nt++)
#pragma unroll
            for (int e = 0; e < 4; e++) acc[m][nt][e] = 0.f;

    for (int d0 = 0; d0 < DD; d0 += 64) {
        __syncthreads();
#pragma unroll
        for (int i = 0; i < 12; i++) {
            int idx = t + i * 128;
            int mat = idx >> 9;        // warp-uniform (i>>2)
            int rr  = idx & 511;
            int r   = rr >> 3;
            int c4  = rr & 7;
            size_t g = (size_t)(d0 + r) * 192 + mat * 64 + c4 * 8;
            uint32_t so = (uint32_t)(mat * 8192 + SWZI(r, c4));
            CP16(sb + PSM_WH + so, g_whi + g);
            if (mat < 2) CP16(sb + PSM_WL + so, g_wlo + g);   // v needs no lo
        }
        CP_COMMIT();
#pragma unroll
        for (int i = 0; i < 4; i++) {
            int idx = t + i * 128;
            int r  = idx >> 3;
            int c4 = idx & 7;
            const float* src = &x[(size_t)(m0 + r) * DD + d0 + c4 * 8];
            float4 f0 = *(const float4*)&src[0];
            float4 f1 = *(const float4*)&src[4];
            uint4 hi, lo;
            hi.x = pkhl(f0.x, f0.y, lo.x);
            hi.y = pkhl(f0.z, f0.w, lo.y);
            hi.z = pkhl(f1.x, f1.y, lo.z);
            hi.w = pkhl(f1.z, f1.w, lo.w);
            int so = SWZI(r, c4);
            *(uint4*)(smc + PSM_XH + so) = hi;
            *(uint4*)(smc + PSM_XL + so) = lo;
        }
        CP_WAIT0();
        __syncthreads();

#pragma unroll
        for (int kt = 0; kt < 4; kt++) {
            unsigned ah[4], al[4];
            uint32_t qa = sb + PSM_XH +
                SWZI(w * 16 + (lane & 15), kt * 2 + (lane >> 4));
            ldsm4(ah, qa);
            ldsm4(al, qa + 8192);
#pragma unroll
            for (int mat = 0; mat < 3; mat++) {
#pragma unroll
                for (int c4t = 0; c4t < 4; c4t++) {
                    int r  = kt * 16 + (((lane >> 3) & 1) << 3) + (lane & 7);
                    int c4 = c4t * 2 + (lane >> 4);
                    unsigned bh[4];
                    ldsm4t(bh, sb + PSM_WH + mat * 8192 + SWZI(r, c4));
#pragma unroll
                    for (int ntl = 0; ntl < 2; ntl++)
                        mma16816(acc[mat][c4t * 2 + ntl], ah, bh + 2 * ntl);
                    if (mat < 2) {
                        unsigned bl[4];
                        ldsm4t(bl, sb + PSM_WL + mat * 8192 + SWZI(r, c4));
#pragma unroll
                        for (int ntl = 0; ntl < 2; ntl++)
                            mma16816(acc[mat][c4t * 2 + ntl], al, bh + 2 * ntl);
#pragma unroll
                        for (int ntl = 0; ntl < 2; ntl++)
                            mma16816(acc[mat][c4t * 2 + ntl], ah, bl + 2 * ntl);
                    }
                }
            }
        }
    }

    const int g  = lane >> 2;
    const int tq = lane & 3;
    const size_t r0 = (size_t)(m0 + w * 16 + g);
    const size_t r1 = r0 + 8;
#pragma unroll
    for (int nt = 0; nt < 8; nt++) {
        int c = nt * 8 + 2 * tq;
        {
            unsigned lo0, lo1;
            unsigned h0 = pkhl(acc[0][nt][0], acc[0][nt][1], lo0);
            unsigned h1 = pkhl(acc[0][nt][2], acc[0][nt][3], lo1);
            *(unsigned*)&g_qhi[r0 * AA + c] = h0;
            *(unsigned*)&g_qlo[r0 * AA + c] = lo0;
            *(unsigned*)&g_qhi[r1 * AA + c] = h1;
            *(unsigned*)&g_qlo[r1 * AA + c] = lo1;
        }
        {
            unsigned lo0, lo1;
            unsigned h0 = pkhl(acc[1][nt][0], acc[1][nt][1], lo0);
            unsigned h1 = pkhl(acc[1][nt][2], acc[1][nt][3], lo1);
            *(unsigned*)&g_khi[r0 * AA + c] = h0;
            *(unsigned*)&g_klo[r0 * AA + c] = lo0;
            *(unsigned*)&g_khi[r1 * AA + c] = h1;
            *(unsigned*)&g_klo[r1 * AA + c] = lo1;
        }
        {
            __half2 v0 = __floats2half2_rn(acc[2][nt][0], acc[2][nt][1]);
            __half2 v1 = __floats2half2_rn(acc[2][nt][2], acc[2][nt][3]);
            *(__half2*)&g_vhi[r0 * AA + c] = v0;
            *(__half2*)&g_vhi[r1 * AA + c] = v1;
        }
    }
}

// ---------------------------------------------------------------------------
// Kernel 2: causal flash attention, fp16 mma.sync, 128-wide k-tiles.
// Q fragments hoisted; l-reduction DEFERRED to epilogue (sc is quad-uniform,
// so per-thread lr partials scale consistently; one 4-lane sum at the end).
// ---------------------------------------------------------------------------
#define SM_QH  0
#define SM_QL  8192
#define SM_KV  16384       // 2 bufs x 48KB: [KH 16K | KL 16K | VH 16K]
#define KVB    49152
#define SM_TOTAL (16384 + 2 * KVB)   // 114688 B = 112 KB

__device__ __forceinline__ void prefetch_kv(uint32_t sb, int buf, size_t gkb, int t)
{
    const uint32_t bb = sb + SM_KV + (uint32_t)buf * KVB;
#pragma unroll
    for (int i = 0; i < 8; i++) {
        int idx = t + i * 128;          // 0..1023 (128 rows x 8 c4)
        int r  = idx >> 3;
        int c4 = idx & 7;
        size_t g = gkb + (size_t)r * AA + c4 * 8;
        uint32_t so = (uint32_t)SWZI(r, c4);
        CP16(bb + so,         g_khi + g);
        CP16(bb + 16384 + so, g_klo + g);
        CP16(bb + 32768 + so, g_vhi + g);
    }
}

__global__ __launch_bounds__(128, 2) void attn_kernel(float* __restrict__ out)
{
    const uint32_t sb = smem_u32(smc);
    const int t    = threadIdx.x;
    const int w    = t >> 5;
    const int lane = t & 31;

    // bid -> (tile, b): pair-sums of ceil((tile+1)/2) are constant 34.
    const int bid = blockIdx.x;
    int tile, b;
    if (bid < 56)       { tile = bid >> 2;              b = bid & 3; }
    else if (bid < 108) { tile = 14 + ((bid - 56) >> 2); b = (bid - 56) & 3; }
    else if (bid < 148) { tile = 40 + ((bid - 108) >> 2); b = (bid - 108) & 3; }
    else if (bid < 204) { tile = 63 - ((bid - 148) >> 2); b = (bid - 148) & 3; }
    else                { tile = 39 - ((bid - 204) >> 2); b = (bid - 204) & 3; }

    const size_t gbase = (size_t)b * LL * AA;
    const int rb = tile * 64 + w * 16;
    const int nsteps = (tile + 2) >> 1;    // ceil((tile+1)/2)

    prefetch_kv(sb, 0, gbase, t);
    CP_COMMIT();

    // Load Q tile (64 rows x 64 fp16, hi+lo).
#pragma unroll
    for (int i = 0; i < 4; i++) {
        int idx = t + i * 128;
        int r  = idx >> 3;
        int c4 = idx & 7;
        size_t g = gbase + (size_t)(tile * 64 + r) * AA + c4 * 8;
        int so = SWZI(r, c4);
        *(uint4*)(smc + SM_QH + so) = *(const uint4*)&g_qhi[g];
        *(uint4*)(smc + SM_QL + so) = *(const uint4*)&g_qlo[g];
    }
    __syncthreads();

    // Hoist Q fragments (jt-invariant).
    unsigned qh4[4][4], ql4[4][4];
#pragma unroll
    for (int kt = 0; kt < 4; kt++) {
        uint32_t qa = sb + SM_QH +
            SWZI(w * 16 + (lane & 15), kt * 2 + (lane >> 4));
        ldsm4(qh4[kt], qa);
        ldsm4(ql4[kt], qa + 8192);
    }

    float O[8][4];
    float mr[2], lr[2];
    mr[0] = mr[1] = -INFF;
    lr[0] = lr[1] = 0.f;          // per-thread partial; reduced in epilogue
#pragma unroll
    for (int nt = 0; nt < 8; nt++)
#pragma unroll
        for (int e = 0; e < 4; e++) O[nt][e] = 0.f;

    const int g  = lane >> 2;
    const int tq = lane & 3;

    for (int jt = 0; jt < nsteps; jt++) {
        const int buf = jt & 1;
        CP_WAIT0();
        __syncthreads();
        if (jt + 1 < nsteps) {
            prefetch_kv(sb, buf ^ 1, gbase + (size_t)(jt + 1) * 128 * AA, t);
            CP_COMMIT();
        }
        const int kb = jt * 128;
        const bool diag = (jt == nsteps - 1);

        float S[16][4];
#pragma unroll
        for (int nt = 0; nt < 16; nt++)
#pragma unroll
            for (int e = 0; e < 4; e++) S[nt][e] = 0.f;

        const uint32_t khb = sb + SM_KV + (uint32_t)buf * KVB;
        const uint32_t klb = khb + 16384;

        // ---- S = Q K^T over 128 k-cols: np in two groups of 4 ----
#pragma unroll
        for (int kt = 0; kt < 4; kt++) {
#pragma unroll
            for (int grp = 0; grp < 2; grp++) {
                unsigned kh4[4][4], kl4[4][4];
#pragma unroll
                for (int n4 = 0; n4 < 4; n4++) {
                    int np = grp * 4 + n4;
                    int r  = np * 16 + ((lane >> 4) << 3) + (lane & 7);
                    int c4 = kt * 2 + ((lane >> 3) & 1);
                    ldsm4(kh4[n4], khb + SWZI(r, c4));
                    ldsm4(kl4[n4], klb + SWZI(r, c4));
                }
#pragma unroll
                for (int n4 = 0; n4 < 4; n4++)
#pragma unroll
                    for (int ntl = 0; ntl < 2; ntl++)
                        mma16816(S[grp * 8 + 2 * n4 + ntl], qh4[kt], kh4[n4] + 2 * ntl);
#pragma unroll
                for (int n4 = 0; n4 < 4; n4++)
#pragma unroll
                    for (int ntl = 0; ntl < 2; ntl++)
                        mma16816(S[grp * 8 + 2 * n4 + ntl], ql4[kt], kh4[n4] + 2 * ntl);
#pragma unroll
                for (int n4 = 0; n4 < 4; n4++)
#pragma unroll
                    for (int ntl = 0; ntl < 2; ntl++)
                        mma16816(S[grp * 8 + 2 * n4 + ntl], qh4[kt], kl4[n4] + 2 * ntl);
            }
        }

        // ---- mask + row max + conditional O rescale ----
        int r0 = rb + g, r1 = r0 + 8;
        if (diag) {
#pragma unroll
            for (int nt = 0; nt < 16; nt++) {
                int col = kb + nt * 8 + 2 * tq;
                if (col     > r0) S[nt][0] = -INFF;
                if (col + 1 > r0) S[nt][1] = -INFF;
                if (col     > r1) S[nt][2] = -INFF;
                if (col + 1 > r1) S[nt][3] = -INFF;
            }
        }
        float m0 = -INFF, m1 = -INFF;
#pragma unroll
        for (int nt = 0; nt < 16; nt++) {
            m0 = fmaxf(m0, fmaxf(S[nt][0], S[nt][1]));
            m1 = fmaxf(m1, fmaxf(S[nt][2], S[nt][3]));
        }
        m0 = fmaxf(m0, __shfl_xor_sync(0xffffffffu, m0, 1));
        m0 = fmaxf(m0, __shfl_xor_sync(0xffffffffu, m0, 2));
        m1 = fmaxf(m1, __shfl_xor_sync(0xffffffffu, m1, 1));
        m1 = fmaxf(m1, __shfl_xor_sync(0xffffffffu, m1, 2));
        float mn0 = fmaxf(mr[0], m0), mn1 = fmaxf(mr[1], m1);
        float sc0 = ex2f(mr[0] - mn0), sc1 = ex2f(mr[1] - mn1);
        mr[0] = mn0; mr[1] = mn1;
        if (__any_sync(0xffffffffu, (sc0 != 1.f) | (sc1 != 1.f))) {
#pragma unroll
            for (int nt = 0; nt < 8; nt++) {
                O[nt][0] *= sc0; O[nt][1] *= sc0;
                O[nt][2] *= sc1; O[nt][3] *= sc1;
            }
        }

        // ---- exp/pack + PV (single pass) ----
        const uint32_t vhb = khb + 32768;
        float rs0 = 0.f, rs1 = 0.f;
#pragma unroll
        for (int ktp = 0; ktp < 8; ktp++) {
            unsigned ph[4];
            {
                float e00 = ex2f(S[2*ktp  ][0] - mn0);
                float e01 = ex2f(S[2*ktp  ][1] - mn0);
                float e02 = ex2f(S[2*ktp  ][2] - mn1);
                float e03 = ex2f(S[2*ktp  ][3] - mn1);
                float e10 = ex2f(S[2*ktp+1][0] - mn0);
                float e11 = ex2f(S[2*ktp+1][1] - mn0);
                float e12 = ex2f(S[2*ktp+1][2] - mn1);
                float e13 = ex2f(S[2*ktp+1][3] - mn1);
                rs0 += (e00 + e01) + (e10 + e11);
                rs1 += (e02 + e03) + (e12 + e13);
                ph[0] = pk16(e00, e01);
                ph[1] = pk16(e02, e03);
                ph[2] = pk16(e10, e11);
                ph[3] = pk16(e12, e13);
            }
            unsigned vh4[4][4];
#pragma unroll
            for (int np = 0; np < 4; np++) {
                int r  = ktp * 16 + (((lane >> 3) & 1) << 3) + (lane & 7);
                int c4 = np * 2 + (lane >> 4);
                ldsm4t(vh4[np], vhb + SWZI(r, c4));
            }
#pragma unroll
            for (int np = 0; np < 4; np++)
#pragma unroll
                for (int ntl = 0; ntl < 2; ntl++)
                    mma16816(O[2 * np + ntl], ph, vh4[np] + 2 * ntl);
        }

        // deferred: lr stays per-thread partial (sc is quad-uniform)
        lr[0] = lr[0] * sc0 + rs0;
        lr[1] = lr[1] * sc1 + rs1;

        __syncthreads();
    }

    // ---- epilogue: reduce lr across the quad once, normalize, store ----
    lr[0] += __shfl_xor_sync(0xffffffffu, lr[0], 1);
    lr[0] += __shfl_xor_sync(0xffffffffu, lr[0], 2);
    lr[1] += __shfl_xor_sync(0xffffffffu, lr[1], 1);
    lr[1] += __shfl_xor_sync(0xffffffffu, lr[1], 2);
    float i0 = 1.f / lr[0], i1 = 1.f / lr[1];
    size_t r0 = (size_t)(rb + g), r1 = r0 + 8;
#pragma unroll
    for (int nt = 0; nt < 8; nt++) {
        *(float2*)&out[gbase + r0 * AA + nt * 8 + 2 * tq] =
            make_float2(O[nt][0] * i0, O[nt][1] * i0);
        *(float2*)&out[gbase + r1 * AA + nt * 8 + 2 * tq] =
            make_float2(O[nt][2] * i1, O[nt][3] * i1);
    }
}

// ---------------------------------------------------------------------------
extern "C" void kernel_launch(void* const* d_in, const int* in_sizes, int n_in,
                              void* d_out, int out_size)
{
    const float* x  = (const float*)d_in[0];
    const float* Wq = (const float*)d_in[1];
    const float* Wk = (const float*)d_in[2];
    const float* Wv = (const float*)d_in[3];
    float* out = (float*)d_out;

    convert_kernel<<<48, 256>>>(Wq, Wk, Wv);

    cudaFuncSetAttribute(qkv_gemm_kernel,
                         cudaFuncAttributeMaxDynamicSharedMemorySize, PSM_TOTAL);
    qkv_gemm_kernel<<<256, 128, PSM_TOTAL>>>(x);

    cudaFuncSetAttribute(attn_kernel,
                         cudaFuncAttributeMaxDynamicSharedMemorySize, SM_TOTAL);
    attn_kernel<<<256, 128, SM_TOTAL>>>(out);
}